// round 17
// baseline (speedup 1.0000x reference)
#include <cuda_runtime.h>
#include <cuda_fp16.h>
#include <mma.h>
#include <math.h>

using namespace nvcuda;

#define Bsz 2
#define Lq  2048
#define Dm  256
#define Hh  8
#define hd  32
#define CH  128
#define NCH 16
#define BHn (Bsz*Hh)
#define EPSf 1e-5f
#define GSC  1024.0f     // gate pre-scale: keeps g*v out of fp16 subnormals

// ---- scratch (device globals; no allocations allowed) ----
__device__ float g_q[BHn*Lq*hd];
__device__ float g_k[BHn*Lq*hd];
__device__ float g_v[BHn*Lq*hd];
__device__ float g_sim[BHn*Lq];
__device__ float g_gate[BHn*Lq];          // stores GSC * gate
__device__ float g_Sc[BHn*NCH*hd*hd];     // scaled by GSC
__device__ float g_gsum[BHn*NCH];         // scaled by GSC
__device__ float g_mc[BHn*NCH];
__device__ float g_scC[BHn*NCH];
// pre-split fp16 hi/lo operands
__device__ __half d_xh[Bsz*Lq*Dm], d_xl[Bsz*Lq*Dm];       // x
__device__ __half d_wh[4*Dm*Dm],   d_wl[4*Dm*Dm];         // wq,wk,wv,wo
__device__ __half d_ch[Bsz*Lq*Dm], d_cl[Bsz*Lq*Dm];       // ctx

__device__ __forceinline__ float warpSum(float v) {
    #pragma unroll
    for (int o = 16; o; o >>= 1) v += __shfl_xor_sync(0xffffffffu, v, o);
    return v;
}
__device__ __forceinline__ float warpMax(float v) {
    #pragma unroll
    for (int o = 16; o; o >>= 1) v = fmaxf(v, __shfl_xor_sync(0xffffffffu, v, o));
    return v;
}
__device__ __forceinline__ float tf32r(float f) { return wmma::__float_to_tf32(f); }

__device__ __forceinline__ void cpa16(unsigned sa, const void* g) {
    asm volatile("cp.async.ca.shared.global [%0], [%1], 16;" :: "r"(sa), "l"(g));
}
#define CP_COMMIT()  asm volatile("cp.async.commit_group;")
#define CP_WAIT(n)   asm volatile("cp.async.wait_group %0;" :: "n"(n))

// ============================================================
// K0: split x and the four weight matrices into fp16 hi/lo.
// ============================================================
__global__ void k_split(const float* __restrict__ x,
                        const float* __restrict__ wq, const float* __restrict__ wk,
                        const float* __restrict__ wv, const float* __restrict__ wo)
{
    int i = blockIdx.x*256 + threadIdx.x;
    const float4* src;
    __half *dh, *dl;
    if (i < 262144) {
        src = (const float4*)x + i;
        dh = d_xh + i*4; dl = d_xl + i*4;
    } else {
        int j = i - 262144;
        int w = j >> 14, off = j & 16383;
        const float* ws = (w==0)?wq:((w==1)?wk:((w==2)?wv:wo));
        src = (const float4*)ws + off;
        dh = d_wh + w*65536 + off*4; dl = d_wl + w*65536 + off*4;
    }
    float4 f = *src;
    __half h0=__float2half_rn(f.x), h1=__float2half_rn(f.y),
           h2=__float2half_rn(f.z), h3=__float2half_rn(f.w);
    ((__half2*)dh)[0] = __halves2half2(h0, h1);
    ((__half2*)dh)[1] = __halves2half2(h2, h3);
    ((__half2*)dl)[0] = __halves2half2(__float2half_rn(f.x-__half2float(h0)),
                                       __float2half_rn(f.y-__half2float(h1)));
    ((__half2*)dl)[1] = __halves2half2(__float2half_rn(f.z-__half2float(h2)),
                                       __float2half_rn(f.w-__half2float(h3)));
}

// ============================================================
// K1: QKV projection, pre-split fp16, cp.async 2-stage pipeline.
// ============================================================
#define STG1 30720
__global__ void k_qkv(const float* __restrict__ bq, const float* __restrict__ bk,
                      const float* __restrict__ bv)
{
    extern __shared__ __align__(16) unsigned char smraw[];
    const unsigned sbase = (unsigned)__cvta_generic_to_shared(smraw);
    const int t   = threadIdx.x;
    const int m0  = blockIdx.x * 128;
    const int mat = blockIdx.y >> 2;
    const int n0  = (blockIdx.y & 3) * 64;
    const __half* Bgh = d_wh + mat*65536;
    const __half* Bgl = d_wl + mat*65536;
    const float* bias = (mat == 0) ? bq : ((mat == 1) ? bk : bv);
    const int warp = t >> 5;
    const int wm = warp >> 1, wn = warp & 1;

    wmma::fragment<wmma::accumulator, 16, 16, 16, float> c[2][2];
    #pragma unroll
    for (int i = 0; i < 2; i++)
        #pragma unroll
        for (int j = 0; j < 2; j++) wmma::fill_fragment(c[i][j], 0.0f);

    auto issue = [&](int s, int k0) {
        unsigned sb = sbase + s*STG1;
        #pragma unroll
        for (int p = 0; p < 2; p++) {
            int slot = t + p*256;
            int row = slot >> 2, seg = slot & 3;
            int go = (m0 + row)*256 + k0 + seg*8;
            unsigned so = row*80 + seg*16;
            cpa16(sb + so,         d_xh + go);
            cpa16(sb + 10240 + so, d_xl + go);
        }
        {
            int row = t >> 2, seg = t & 3;
            int go = (n0 + row)*256 + k0 + seg*8;
            unsigned so = row*80 + seg*16;
            cpa16(sb + 20480 + so, Bgh + go);
            cpa16(sb + 25600 + so, Bgl + go);
        }
    };

    issue(0, 0); CP_COMMIT();
    int buf = 0;
    for (int it = 0; it < 8; it++) {
        if (it < 7) { issue(buf^1, (it+1)*32); CP_COMMIT(); CP_WAIT(1); }
        else        { CP_WAIT(0); }
        __syncthreads();
        const __half* Ah = (const __half*)(smraw + buf*STG1);
        const __half* Al = Ah + 5120;
        const __half* Bh = Ah + 10240;
        const __half* Bl = Ah + 12800;
        #pragma unroll
        for (int kk = 0; kk < 2; kk++) {
            wmma::fragment<wmma::matrix_a, 16, 16, 16, __half, wmma::row_major> ah[2], al[2];
            wmma::fragment<wmma::matrix_b, 16, 16, 16, __half, wmma::col_major> bh[2], bl[2];
            #pragma unroll
            for (int i = 0; i < 2; i++) {
                wmma::load_matrix_sync(ah[i], Ah + (wm*32 + i*16)*40 + kk*16, 40);
                wmma::load_matrix_sync(al[i], Al + (wm*32 + i*16)*40 + kk*16, 40);
            }
            #pragma unroll
            for (int j = 0; j < 2; j++) {
                wmma::load_matrix_sync(bh[j], Bh + (wn*32 + j*16)*40 + kk*16, 40);
                wmma::load_matrix_sync(bl[j], Bl + (wn*32 + j*16)*40 + kk*16, 40);
            }
            #pragma unroll
            for (int i = 0; i < 2; i++)
                #pragma unroll
                for (int j = 0; j < 2; j++) {
                    wmma::mma_sync(c[i][j], ah[i], bh[j], c[i][j]);
                    wmma::mma_sync(c[i][j], al[i], bh[j], c[i][j]);
                    wmma::mma_sync(c[i][j], ah[i], bl[j], c[i][j]);
                }
        }
        __syncthreads();
        buf ^= 1;
    }
    float* Cs = (float*)smraw;
    #pragma unroll
    for (int i = 0; i < 2; i++)
        #pragma unroll
        for (int j = 0; j < 2; j++)
            wmma::store_matrix_sync(&Cs[(wm*32 + i*16)*64 + wn*32 + j*16], c[i][j], 64, wmma::mem_row_major);
    __syncthreads();
    float* dst = (mat == 0) ? g_q : ((mat == 1) ? g_k : g_v);
    for (int idx = t; idx < 128*64; idx += 256) {
        int row = idx >> 6, col = idx & 63;
        int m = m0 + row;
        int b = m >> 11, l = m & 2047;
        int o = n0 + col;
        int hidx = o >> 5, d = o & 31;
        dst[((b*Hh + hidx)*Lq + l)*hd + d] = Cs[idx] + bias[o];
    }
}

// ============================================================
// K2: preprocess: thread-pair per position, TC gate, chunk sums.
// Gates stored pre-scaled by GSC (exact algebra; see dinv in k_intra).
// ============================================================
#define PREP_SMEM 58880
__global__ void k_prepchunk(const float* __restrict__ wg, const float* __restrict__ wgb,
                            const float* __restrict__ kvs, const float* __restrict__ qks)
{
    extern __shared__ float ps[];
    float* Ksh = ps;
    float* Vsh = ps + 4608;
    float* Msh = ps + 9216;
    float* Tsh = ps + 10368;
    float* gsh = ps + 14464;
    float* ssh = ps + 14592;
    const int tid = threadIdx.x;
    const int bx = blockIdx.x, bh = bx >> 4, c = bx & 15, h = bh & 7;
    const int warp = tid >> 5;

    for (int idx = tid; idx < 1024; idx += 256) {
        int d = idx >> 5, e = idx & 31;
        Msh[d*36 + e] = tf32r(kvs[h*1024 + idx] * wg[idx]);
    }
    const float qscale = qks[h];
    const float wb0 = wgb[0];
    const int pos = tid >> 1, hf = tid & 1;
    const int gbase = (bh*Lq + c*CH + pos)*hd + hf*16;

    float4 kr[4], vr[4];
    float qk = 0.f, kk = 0.f, vv = 0.f;
    #pragma unroll
    for (int j = 0; j < 4; j++) {
        float4 q4 = *(const float4*)&g_q[gbase + j*4];
        kr[j] = *(const float4*)&g_k[gbase + j*4];
        vr[j] = *(const float4*)&g_v[gbase + j*4];
        qk += q4.x*kr[j].x + q4.y*kr[j].y + q4.z*kr[j].z + q4.w*kr[j].w;
        kk += kr[j].x*kr[j].x + kr[j].y*kr[j].y + kr[j].z*kr[j].z + kr[j].w*kr[j].w;
        vv += vr[j].x*vr[j].x + vr[j].y*vr[j].y + vr[j].z*vr[j].z + vr[j].w*vr[j].w;
    }
    qk += __shfl_xor_sync(0xffffffffu, qk, 1);
    kk += __shfl_xor_sync(0xffffffffu, kk, 1);
    vv += __shfl_xor_sync(0xffffffffu, vv, 1);
    float sim = qk * qscale;
    float kin = 1.f / fmaxf(sqrtf(kk), 1e-12f);
    float vin = 1.f / fmaxf(sqrtf(vv), 1e-12f);
    #pragma unroll
    for (int j = 0; j < 4; j++) {
        kr[j].x *= kin; kr[j].y *= kin; kr[j].z *= kin; kr[j].w *= kin;
        vr[j].x *= vin; vr[j].y *= vin; vr[j].z *= vin; vr[j].w *= vin;
        *(float4*)&g_k[gbase + j*4] = kr[j];
        *(float4*)&g_v[gbase + j*4] = vr[j];
        float* kd = &Ksh[pos*36 + hf*16 + j*4];
        kd[0]=tf32r(kr[j].x); kd[1]=tf32r(kr[j].y); kd[2]=tf32r(kr[j].z); kd[3]=tf32r(kr[j].w);
        float* vd = &Vsh[pos*36 + hf*16 + j*4];
        vd[0]=tf32r(vr[j].x); vd[1]=tf32r(vr[j].y); vd[2]=tf32r(vr[j].z); vd[3]=tf32r(vr[j].w);
    }
    if (hf == 0) { ssh[pos] = sim; g_sim[bh*Lq + c*CH + pos] = sim; }
    __syncthreads();

    {
        wmma::fragment<wmma::accumulator, 16, 16, 8, float> ct[2];
        wmma::fill_fragment(ct[0], 0.f); wmma::fill_fragment(ct[1], 0.f);
        #pragma unroll
        for (int ks = 0; ks < 4; ks++) {
            wmma::fragment<wmma::matrix_a, 16, 16, 8, wmma::precision::tf32, wmma::row_major> a;
            wmma::load_matrix_sync(a, &Ksh[(warp*16)*36 + ks*8], 36);
            #pragma unroll
            for (int jn = 0; jn < 2; jn++) {
                wmma::fragment<wmma::matrix_b, 16, 16, 8, wmma::precision::tf32, wmma::col_major> bm;
                wmma::load_matrix_sync(bm, &Msh[(jn*16)*36 + ks*8], 36);
                wmma::mma_sync(ct[jn], a, bm, ct[jn]);
            }
        }
        wmma::store_matrix_sync(&Tsh[(warp*16)*32 + 0],  ct[0], 32, wmma::mem_row_major);
        wmma::store_matrix_sync(&Tsh[(warp*16)*32 + 16], ct[1], 32, wmma::mem_row_major);
    }
    __syncthreads();

    {
        float dot = 0.f;
        #pragma unroll
        for (int j = 0; j < 4; j++) {
            float4 t4 = *(const float4*)&Tsh[pos*32 + hf*16 + j*4];
            float4 v4 = *(const float4*)&Vsh[pos*36 + hf*16 + j*4];
            dot += t4.x*v4.x + t4.y*v4.y + t4.z*v4.z + t4.w*v4.w;
        }
        dot += __shfl_xor_sync(0xffffffffu, dot, 1);
        if (hf == 0) {
            float r = fmaxf(dot + wb0, 0.f);
            float gate = (r*r + EPSf) * GSC;       // pre-scaled gate
            gsh[pos] = gate;
            g_gate[bh*Lq + c*CH + pos] = gate;
        }
    }
    __syncthreads();

    const int d = tid >> 3, e0 = (tid & 7)*4;
    float4 acc = {0.f, 0.f, 0.f, 0.f};
    for (int i = 0; i < CH; i++) {
        float cfv = gsh[i] * Vsh[i*36 + d];
        float4 k4 = *(const float4*)&Ksh[i*36 + e0];
        acc.x += cfv*k4.x; acc.y += cfv*k4.y; acc.z += cfv*k4.z; acc.w += cfv*k4.w;
    }
    *(float4*)&g_Sc[bx*1024 + tid*4] = acc;
    if (tid < 32) {
        float m = -1e30f;
        #pragma unroll
        for (int k = 0; k < 4; k++) m = fmaxf(m, ssh[tid + 32*k]);
        m = warpMax(m);
        float s = 0.f, gsum = 0.f;
        #pragma unroll
        for (int k = 0; k < 4; k++) { s += __expf(ssh[tid + 32*k] - m); gsum += gsh[tid + 32*k]; }
        s = warpSum(s); gsum = warpSum(gsum);
        if (tid == 0) { g_mc[bx] = m; g_scC[bx] = s; g_gsum[bx] = gsum; }
    }
}

// ============================================================
// K3: intra-chunk, fp16 HMMA with GSC-scaled gates (no subnormals).
// byte layout: Qsh h[128x40]@0 | Ksh@10240 | Vgh@20480 | SPh h[4x32x40]@30720
//              Pan f[5120]@40960 | cfh h[8x16x40]@61440
//              rawg@71680 simA@72192 ws@72704 dinv@73216 agg@73728 misc@73776
// ============================================================
#define SMEM_INTRA 73792

__global__ void k_intra()
{
    extern __shared__ __align__(16) unsigned char smb[];
    __half* Qsh = (__half*)smb;
    __half* Ksh = (__half*)(smb + 10240);
    __half* Vgh = (__half*)(smb + 20480);
    __half* SPh = (__half*)(smb + 30720);
    float*  Pan = (float*)(smb + 40960);
    __half* cfh = (__half*)(smb + 61440);
    float*  rawg = (float*)(smb + 71680);
    float*  simA = (float*)(smb + 72192);
    float*  ws   = (float*)(smb + 72704);
    float*  dinv = (float*)(smb + 73216);
    float*  aggM = (float*)(smb + 73728);
    float*  aggS = aggM + 4;
    float*  aggG = aggM + 8;
    float*  misc = (float*)(smb + 73776);

    const int tid = threadIdx.x;
    const int bx  = blockIdx.x;
    const int bh  = bx >> 4, c = bx & 15;
    const int b   = bh >> 3, h = bh & 7;
    const int gb  = (bh*Lq + c*CH)*hd;
    const int warp = tid >> 5, lane = tid & 31;

    // ---- front-loaded tile LDGs; Q,K stored as fp16, V persists ----
    float4 vr[4];
    #pragma unroll
    for (int p = 0; p < 4; p++) {
        int idx = tid*4 + p*1024;
        float4 q4 = *(const float4*)&g_q[gb + idx];
        float4 k4 = *(const float4*)&g_k[gb + idx];
        vr[p]     = *(const float4*)&g_v[gb + idx];
        int i = idx >> 5, dd = idx & 31;
        __half2* qd = (__half2*)&Qsh[i*40 + dd];
        qd[0] = __floats2half2_rn(q4.x, q4.y);
        qd[1] = __floats2half2_rn(q4.z, q4.w);
        __half2* kd = (__half2*)&Ksh[i*40 + dd];
        kd[0] = __floats2half2_rn(k4.x, k4.y);
        kd[1] = __floats2half2_rn(k4.z, k4.w);
    }
    if (tid < CH) {
        rawg[tid] = g_gate[bh*Lq + c*CH + tid];
        simA[tid] = g_sim [bh*Lq + c*CH + tid];
    }
    // chunk-state exclusive prefix -> SPh[0] fp16 + SP0 fp32 in Pan[0..1279]
    {
        int d = tid >> 3, e0 = (tid & 7)*4;
        float4 a = {0.f, 0.f, 0.f, 0.f};
        for (int cc = 0; cc < c; cc++) {
            float4 v = *(const float4*)&g_Sc[(bh*NCH + cc)*1024 + tid*4];
            a.x += v.x; a.y += v.y; a.z += v.z; a.w += v.w;
        }
        __half2* dst = (__half2*)&SPh[d*40 + e0];
        dst[0] = __floats2half2_rn(a.x, a.y);
        dst[1] = __floats2half2_rn(a.z, a.w);
        *(float4*)&Pan[d*40 + e0] = a;
    }
    // misc: warp-parallel combine over chunks < c
    if (warp == 0) {
        float mc = -1e30f, sc = 0.f, gg = 0.f;
        if (lane < c) {
            int i = bh*NCH + lane;
            mc = g_mc[i]; sc = g_scC[i]; gg = g_gsum[i];
        }
        float m  = warpMax(mc);
        float s  = warpSum(sc * __expf(mc - m));
        float gp = warpSum(gg);
        if (lane == 0) { misc[0] = m; misc[1] = s; misc[2] = gp; }
    }
    __syncthreads();

    // Vg = g̃ * v (fp16; g̃ = GSC*g keeps entries normal-range)
    #pragma unroll
    for (int p = 0; p < 4; p++) {
        int idx = tid*4 + p*1024;
        int i = idx >> 5, dd = idx & 31;
        float g = rawg[i];
        __half2* vd = (__half2*)&Vgh[i*40 + dd];
        vd[0] = __floats2half2_rn(vr[p].x*g, vr[p].y*g);
        vd[1] = __floats2half2_rn(vr[p].z*g, vr[p].w*g);
    }

    // ---- warp-shfl inclusive scans ----
    float mval = 0.f, sval = 0.f, gval = 0.f, sim0 = 0.f;
    if (tid < CH) {
        sim0 = simA[tid];
        mval = sim0; sval = 1.f; gval = rawg[tid];
        #pragma unroll
        for (int off = 1; off < 32; off <<= 1) {
            float m2 = __shfl_up_sync(0xffffffffu, mval, off);
            float s2 = __shfl_up_sync(0xffffffffu, sval, off);
            float g2 = __shfl_up_sync(0xffffffffu, gval, off);
            if (lane >= off) {
                float mn = fmaxf(mval, m2);
                sval = sval*__expf(mval - mn) + s2*__expf(m2 - mn);
                mval = mn;
                gval += g2;
            }
        }
        if (lane == 31) { aggM[warp] = mval; aggS[warp] = sval; aggG[warp] = gval; }
    }
    __syncthreads();
    if (tid < CH) {
        float mp = misc[0], sp = misc[1], gp = misc[2];
        for (int ww = 0; ww < warp; ww++) {
            float ma = aggM[ww], sa = aggS[ww];
            float mn = fmaxf(mp, ma);
            sp = sp*__expf(mp - mn) + sa*__expf(ma - mn);
            mp = mn;
            gp += aggG[ww];
        }
        float mn = fmaxf(mp, mval);
        float st = sp*__expf(mp - mn) + sval*__expf(mval - mn);
        float sw = __expf(sim0 - mn) / (st + EPSf);
        ws[tid]   = 1.f + sw / (1.f + __expf(-sw));
        dinv[tid] = 1.f / (gp + gval + GSC*EPSf);   // scaled-gate algebra
    }

    // ---- Ssub_j = Vg_j^T @ K_j (fp16 HMMA) -> Pan[(j+1)*1280] fp32 ----
    {
        int task = -1;
        if (warp >= 4) task = warp - 4;
        else if (warp < 2) task = 4 + warp;
        if (task >= 0) {
            int j = task >> 1, hh = task & 1;
            wmma::fragment<wmma::accumulator, 16, 16, 16, float> cs[2];
            wmma::fill_fragment(cs[0], 0.0f);
            wmma::fill_fragment(cs[1], 0.0f);
            #pragma unroll
            for (int kk = 0; kk < 2; kk++) {
                wmma::fragment<wmma::matrix_a, 16, 16, 16, __half, wmma::col_major> a;
                wmma::load_matrix_sync(a, &Vgh[(j*32 + kk*16)*40 + hh*16], 40);
                #pragma unroll
                for (int jn = 0; jn < 2; jn++) {
                    wmma::fragment<wmma::matrix_b, 16, 16, 16, __half, wmma::row_major> bm;
                    wmma::load_matrix_sync(bm, &Ksh[(j*32 + kk*16)*40 + jn*16], 40);
                    wmma::mma_sync(cs[jn], a, bm, cs[jn]);
                }
            }
            #pragma unroll
            for (int jn = 0; jn < 2; jn++)
                wmma::store_matrix_sync(&Pan[(j+1)*1280 + hh*16*40 + jn*16], cs[jn], 40, wmma::mem_row_major);
        }
    }
    __syncthreads();

    // ---- SP prefix: SPh[j+1] = fp16(SP0_fp32 + sum_{<=j} Ssub) ----
    {
        int d = tid >> 3, e0 = (tid & 7)*4;
        int off = d*40 + e0;
        float a0 = Pan[off+0], a1 = Pan[off+1], a2 = Pan[off+2], a3 = Pan[off+3];
        #pragma unroll
        for (int j = 0; j < 3; j++) {
            a0 += Pan[(j+1)*1280 + off+0]; a1 += Pan[(j+1)*1280 + off+1];
            a2 += Pan[(j+1)*1280 + off+2]; a3 += Pan[(j+1)*1280 + off+3];
            __half2* dst = (__half2*)&SPh[(j+1)*1280 + off];
            dst[0] = __floats2half2_rn(a0, a1);
            dst[1] = __floats2half2_rn(a2, a3);
        }
    }
    __syncthreads();

    // ---- per-warp output: rows [16w,16w+16), sb = w/2 (fp16 HMMA) ----
    const int r0 = warp * 16, sb = warp >> 1;
    float*  myPan = &Pan[warp*640];
    __half* mycf  = &cfh[warp*640];

    wmma::fragment<wmma::accumulator, 16, 16, 16, float> cY[2], cP[2];
    wmma::fill_fragment(cY[0], 0.0f); wmma::fill_fragment(cY[1], 0.0f);
    wmma::fill_fragment(cP[0], 0.0f); wmma::fill_fragment(cP[1], 0.0f);
    #pragma unroll
    for (int kk = 0; kk < 2; kk++) {
        wmma::fragment<wmma::matrix_a, 16, 16, 16, __half, wmma::row_major> a;
        wmma::load_matrix_sync(a, &Qsh[r0*40 + kk*16], 40);
        #pragma unroll
        for (int jn = 0; jn < 2; jn++) {
            wmma::fragment<wmma::matrix_b, 16, 16, 16, __half, wmma::row_major> bS;
            wmma::load_matrix_sync(bS, &SPh[sb*1280 + (kk*16)*40 + jn*16], 40);
            wmma::mma_sync(cY[jn], a, bS, cY[jn]);
            wmma::fragment<wmma::matrix_b, 16, 16, 16, __half, wmma::col_major> bV;
            wmma::load_matrix_sync(bV, &Vgh[(sb*32 + jn*16)*40 + kk*16], 40);
            wmma::mma_sync(cP[jn], a, bV, cP[jn]);
        }
    }
    wmma::store_matrix_sync(&myPan[0],  cP[0], 40, wmma::mem_row_major);
    wmma::store_matrix_sync(&myPan[16], cP[1], 40, wmma::mem_row_major);
    __syncwarp();
    // mask + convert to fp16 cf
    {
        int base_th = (warp & 1) << 4;
        #pragma unroll
        for (int e = 0; e < 16; e++) {
            int idx = lane + e*32;
            int rr = idx >> 5, ii = idx & 31;
            float val = myPan[rr*40 + ii];
            mycf[rr*40 + ii] = (ii <= base_th + rr) ? __float2half_rn(val) : __half(0.f);
        }
    }
    __syncwarp();
    #pragma unroll
    for (int kk = 0; kk < 2; kk++) {
        wmma::fragment<wmma::matrix_a, 16, 16, 16, __half, wmma::row_major> a;
        wmma::load_matrix_sync(a, &mycf[kk*16], 40);
        #pragma unroll
        for (int jn = 0; jn < 2; jn++) {
            wmma::fragment<wmma::matrix_b, 16, 16, 16, __half, wmma::row_major> bm;
            wmma::load_matrix_sync(bm, &Ksh[(sb*32 + kk*16)*40 + jn*16], 40);
            wmma::mma_sync(cY[jn], a, bm, cY[jn]);
        }
    }
    wmma::store_matrix_sync(&myPan[0],  cY[0], 40, wmma::mem_row_major);
    wmma::store_matrix_sync(&myPan[16], cY[1], 40, wmma::mem_row_major);
    __syncwarp();
    #pragma unroll
    for (int rr = 0; rr < 16; rr++) {
        int r = r0 + rr;
        float y = myPan[rr*40 + lane] * ws[r] * dinv[r];
        int cidx = (b*Lq + c*CH + r)*Dm + h*hd + lane;
        __half hy = __float2half_rn(y);
        d_ch[cidx] = hy;
        d_cl[cidx] = __float2half_rn(y - __half2float(hy));
    }
}

// ============================================================
// K4: output projection, pre-split fp16 + cp.async.
// ============================================================
#define STG2 20480
__global__ void k_out(const float* __restrict__ bo, float* __restrict__ out)
{
    extern __shared__ __align__(16) unsigned char smraw[];
    const unsigned sbase = (unsigned)__cvta_generic_to_shared(smraw);
    const int t  = threadIdx.x;
    const int m0 = blockIdx.x * 64;
    const int n0 = blockIdx.y * 64;
    const __half* Bgh = d_wh + 3*65536;
    const __half* Bgl = d_wl + 3*65536;
    const int warp = t >> 5;
    const int wm = warp >> 1, wn = warp & 1;

    wmma::fragment<wmma::accumulator, 16, 16, 16, float> c[2];
    wmma::fill_fragment(c[0], 0.0f);
    wmma::fill_fragment(c[1], 0.0f);

    auto issue = [&](int s, int k0) {
        unsigned sb = sbase + s*STG2;
        int row = t >> 2, seg = t & 3;
        unsigned so = row*80 + seg*16;
        int ga = (m0 + row)*256 + k0 + seg*8;
        int gbb = (n0 + row)*256 + k0 + seg*8;
        cpa16(sb + so,         d_ch + ga);
        cpa16(sb + 5120 + so,  d_cl + ga);
        cpa16(sb + 10240 + so, Bgh + gbb);
        cpa16(sb + 15360 + so, Bgl + gbb);
    };

    issue(0, 0); CP_COMMIT();
    int buf = 0;
    for (int it = 0; it < 8; it++) {
        if (it < 7) { issue(buf^1, (it+1)*32); CP_COMMIT(); CP_WAIT(1); }
        else        { CP_WAIT(0); }
        __syncthreads();
        const __half* Ah = (const __half*)(smraw + buf*STG2);
        const __half* Al = Ah + 2560;
        const __half* Bh = Ah + 5120;
        const __half* Bl = Ah + 7680;
        #pragma unroll
        for (int kk = 0; kk < 2; kk++) {
            wmma::fragment<wmma::matrix_a, 16, 16, 16, __half, wmma::row_major> ah, al;
            wmma::fragment<wmma::matrix_b, 16, 16, 16, __half, wmma::col_major> bh[2], bl[2];
            wmma::load_matrix_sync(ah, Ah + (wm*16)*40 + kk*16, 40);
            wmma::load_matrix_sync(al, Al + (wm*16)*40 + kk*16, 40);
            #pragma unroll
            for (int j = 0; j < 2; j++) {
                wmma::load_matrix_sync(bh[j], Bh + (wn*32 + j*16)*40 + kk*16, 40);
                wmma::load_matrix_sync(bl[j], Bl + (wn*32 + j*16)*40 + kk*16, 40);
            }
            #pragma unroll
            for (int j = 0; j < 2; j++) {
                wmma::mma_sync(c[j], ah, bh[j], c[j]);
                wmma::mma_sync(c[j], al, bh[j], c[j]);
                wmma::mma_sync(c[j], ah, bl[j], c[j]);
            }
        }
        __syncthreads();
        buf ^= 1;
    }
    float* Cs = (float*)smraw;
    #pragma unroll
    for (int j = 0; j < 2; j++)
        wmma::store_matrix_sync(&Cs[(wm*16)*64 + wn*32 + j*16], c[j], 64, wmma::mem_row_major);
    __syncthreads();
    for (int idx = t; idx < 64*64; idx += 256) {
        int row = idx >> 6, col = idx & 63;
        int o = n0 + col;
        out[(m0 + row)*256 + o] = Cs[idx] + bo[o];
    }
}

// ============================================================
extern "C" void kernel_launch(void* const* d_in, const int* in_sizes, int n_in,
                              void* d_out, int out_size)
{
    const float* x   = (const float*)d_in[0];
    const float* wq  = (const float*)d_in[1];
    const float* bq  = (const float*)d_in[2];
    const float* wk  = (const float*)d_in[3];
    const float* bk  = (const float*)d_in[4];
    const float* wv  = (const float*)d_in[5];
    const float* bv  = (const float*)d_in[6];
    const float* wo  = (const float*)d_in[7];
    const float* bo  = (const float*)d_in[8];
    const float* wg  = (const float*)d_in[9];
    const float* wgb = (const float*)d_in[10];
    const float* kvs = (const float*)d_in[11];
    const float* qks = (const float*)d_in[12];
    float* out = (float*)d_out;

    cudaFuncSetAttribute(k_qkv,       cudaFuncAttributeMaxDynamicSharedMemorySize, 2*STG1);
    cudaFuncSetAttribute(k_prepchunk, cudaFuncAttributeMaxDynamicSharedMemorySize, PREP_SMEM);
    cudaFuncSetAttribute(k_intra,     cudaFuncAttributeMaxDynamicSharedMemorySize, SMEM_INTRA);
    cudaFuncSetAttribute(k_out,       cudaFuncAttributeMaxDynamicSharedMemorySize, 2*STG2);

    k_split    <<<1280, 256>>>(x, wq, wk, wv, wo);
    k_qkv      <<<dim3(32, 12), 256, 2*STG1>>>(bq, bk, bv);
    k_prepchunk<<<256, 256, PREP_SMEM>>>(wg, wgb, kvs, qks);
    k_intra    <<<256, 256, SMEM_INTRA>>>();
    k_out      <<<dim3(64, 4), 256, 2*STG2>>>(bo, out);
}